// round 16
// baseline (speedup 1.0000x reference)
#include <cuda_runtime.h>
#include <math.h>

// Problem constants
#define Bb 2
#define Cc 64
#define Nn 8192
#define Oo 64
#define Kk 20
#define NPOINTS (Bb * Nn)            // 16384
#define MROWS   (NPOINTS * Kk)       // 327680
#define SEG 48                       // slots per (row, column-tile) segment
#define NTILE 64                     // column tiles per row
#define CAND_SLOTS (NTILE * SEG)     // 3072 slots per row
#define DCAP 1536                    // dense per-row candidate cap in k_sel

// ---------------- scratch (device globals; allocation-free) ----------------
__device__ float  g_xt[NPOINTS * Cc];   // [B*N][C]   transposed points
__device__ float  g_sq[NPOINTS];        // ||x||^2 per point
__device__ float  g_xsT[Bb * Cc * 256]; // gathered sample points, [b][c][s]
__device__ float  g_sqs[Bb * 256];      // sample sq
__device__ float  g_sdist[NPOINTS * 256]; // sample distances per row
__device__ float  g_thr[NPOINTS];       // per-row threshold
__device__ float  g_candv[(size_t)NPOINTS * CAND_SLOTS];
__device__ int    g_candi[(size_t)NPOINTS * CAND_SLOTS];
__device__ int    g_tc[NPOINTS * NTILE]; // per (row, tile) survivor count
__device__ int    g_idx[MROWS];         // top-K indices, [B*N][K]
__device__ float  g_u[NPOINTS * Oo];    // center term (W2-W1)·cen
__device__ float  g_y[NPOINTS * Oo];    // neighbor term W1·x per point
__device__ double g_sum[Oo];
__device__ double g_sumsq[Oo];
__device__ float  g_sc[Oo];
__device__ float  g_sh[Oo];

// monotonic float <-> sortable uint mapping
__device__ __forceinline__ unsigned f2key(float f) {
    unsigned u = __float_as_uint(f);
    return (u & 0x80000000u) ? ~u : (u | 0x80000000u);
}
__device__ __forceinline__ float key2f(unsigned m) {
    return __uint_as_float((m & 0x80000000u) ? (m & 0x7FFFFFFFu) : ~m);
}

// ---------------- packed fp32x2 helpers (B300 FFMA2 path, PTX-only) --------
__device__ __forceinline__ unsigned long long dup2(float a) {
    unsigned long long r;
    asm("mov.b64 %0, {%1, %1};" : "=l"(r) : "f"(a));
    return r;
}
__device__ __forceinline__ void fma2(unsigned long long& d, unsigned long long a,
                                     unsigned long long b) {
    asm("fma.rn.f32x2 %0, %1, %2, %0;" : "+l"(d) : "l"(a), "l"(b));
}
__device__ __forceinline__ float2 unpk(unsigned long long v) {
    float2 r;
    asm("mov.b64 {%0, %1}, %2;" : "=f"(r.x), "=f"(r.y) : "l"(v));
    return r;
}

// ---------------- kernel 0: zero accumulators ----------------
__global__ void k_zero() {
    int t = threadIdx.x;
    if (t < Oo) { g_sum[t] = 0.0; g_sumsq[t] = 0.0; }
}

// ---------------- kernel 1: transpose x -> xt, sq, gather samples ---------
// Sample positions: pos(s) = s*32 + (s&31), s in [0,256).
__global__ void k_prep(const float* __restrict__ x) {
    int p = blockIdx.x * 256 + threadIdx.x;   // 0..16383
    int b = p >> 13;
    int n = p & (Nn - 1);
    const float* xb = x + (size_t)b * Cc * Nn;
    bool is_s = ((n & 31) == ((n >> 5) & 31));
    int s = n >> 5;
    float sm = 0.f;
    #pragma unroll
    for (int c = 0; c < Cc; c++) {
        float v = xb[c * Nn + n];
        sm += v * v;
        g_xt[(size_t)p * Cc + c] = v;
        if (is_s) g_xsT[(b * Cc + c) * 256 + s] = v;
    }
    g_sq[p] = sm;
    if (is_s) g_sqs[b * 256 + s] = sm;
}

// ---------------- kernel 2a: sample-dist GEMM (rows x 256 samples) --------
#define DSTRIDE 132
__global__ void k_samp(const float* __restrict__ x) {
    extern __shared__ float sm[];
    float* As = sm;
    float* Bs = sm + 64 * DSTRIDE;
    const int b  = blockIdx.z;
    const int i0 = blockIdx.y * 128;
    const int j0 = blockIdx.x * 128;
    const int tid = threadIdx.x;
    const float* xb = x + (size_t)b * Cc * Nn;

    for (int L = tid; L < 2048; L += 256) {
        int c = L >> 5, q = L & 31;
        float4 v = *(const float4*)(xb + c * Nn + i0 + q * 4);
        *(float4*)(As + c * DSTRIDE + q * 4) = v;
        float4 w = *(const float4*)(g_xsT + (b * Cc + c) * 256 + j0 + q * 4);
        *(float4*)(Bs + c * DSTRIDE + q * 4) = w;
    }
    __syncthreads();

    int tx = tid & 15, ty = tid >> 4;
    unsigned long long acc2[8][4];
    #pragma unroll
    for (int i = 0; i < 8; i++)
        #pragma unroll
        for (int q = 0; q < 4; q++) acc2[i][q] = 0ull;

    #pragma unroll 4
    for (int kk = 0; kk < 64; kk++) {
        ulonglong2 bb0 = *(const ulonglong2*)(Bs + kk * DSTRIDE + tx * 8);
        ulonglong2 bb1 = *(const ulonglong2*)(Bs + kk * DSTRIDE + tx * 8 + 4);
        float4 a0 = *(const float4*)(As + kk * DSTRIDE + ty * 8);
        float4 a1 = *(const float4*)(As + kk * DSTRIDE + ty * 8 + 4);
        float a[8] = {a0.x, a0.y, a0.z, a0.w, a1.x, a1.y, a1.z, a1.w};
        #pragma unroll
        for (int i = 0; i < 8; i++) {
            unsigned long long ap = dup2(a[i]);
            fma2(acc2[i][0], ap, bb0.x);
            fma2(acc2[i][1], ap, bb0.y);
            fma2(acc2[i][2], ap, bb1.x);
            fma2(acc2[i][3], ap, bb1.y);
        }
    }

    float sqj[8];
    #pragma unroll
    for (int j = 0; j < 8; j++) sqj[j] = g_sqs[b * 256 + j0 + tx * 8 + j];
    #pragma unroll
    for (int i = 0; i < 8; i++) {
        float sqi = g_sq[b * Nn + i0 + ty * 8 + i];
        float* dst = g_sdist + (size_t)(b * Nn + i0 + ty * 8 + i) * 256 + j0 + tx * 8;
        float2 p0 = unpk(acc2[i][0]);
        float2 p1 = unpk(acc2[i][1]);
        float2 p2 = unpk(acc2[i][2]);
        float2 p3 = unpk(acc2[i][3]);
        float4 r0, r1;
        r0.x = 2.f * p0.x - sqi - sqj[0];
        r0.y = 2.f * p0.y - sqi - sqj[1];
        r0.z = 2.f * p1.x - sqi - sqj[2];
        r0.w = 2.f * p1.y - sqi - sqj[3];
        r1.x = 2.f * p2.x - sqi - sqj[4];
        r1.y = 2.f * p2.y - sqi - sqj[5];
        r1.z = 2.f * p3.x - sqi - sqj[6];
        r1.w = 2.f * p3.y - sqi - sqj[7];
        *(float4*)dst = r0;
        *(float4*)(dst + 4) = r1;
    }
}

// ---------------- kernel 2b: per-row threshold = 12th largest sample ------
__global__ __launch_bounds__(256) void k_thr() {
    int lane = threadIdx.x & 31;
    int row  = blockIdx.x * 8 + (threadIdx.x >> 5);
    const float* sd = g_sdist + (size_t)row * 256;
    float lv[8];
    #pragma unroll
    for (int s = 0; s < 8; s++) lv[s] = sd[lane + 32 * s];
    for (int k = 0; ; k++) {
        float lmax = lv[0];
        #pragma unroll
        for (int s = 1; s < 8; s++) lmax = fmaxf(lmax, lv[s]);
        unsigned key = f2key(lmax);
        unsigned m = __reduce_max_sync(0xffffffffu, key);
        if (k == 11) { if (lane == 0) g_thr[row] = key2f(m); break; }
        int win = __ffs(__ballot_sync(0xffffffffu, key == m)) - 1;
        if (lane == win) {
            bool done = false;
            #pragma unroll
            for (int s = 0; s < 8; s++)
                if (!done && lv[s] == lmax) { lv[s] = -INFINITY; done = true; }
        }
    }
}

// ---------------- kernel 3: symmetric dist GEMM + fixed-slot filter -------
// Upper-triangle tiles only (jb >= ib). Survivors written directly to
// reserved per-(row,tile) global slots; exactly one writer per segment,
// NO atomics. Counts in g_tc; overflow detected in k_sel -> exact fallback.
#define VST 129
__global__ __launch_bounds__(256) void k_dist_sym(const float* __restrict__ x) {
    extern __shared__ float sm[];
    float* As = sm;
    float* Bs = sm + 64 * DSTRIDE;
    __shared__ float s_thri[128], s_thrj[128], s_sqi[128], s_sqj[128];

    const int b  = blockIdx.z;
    const int ib = blockIdx.y;
    const int jb = blockIdx.x;
    if (jb < ib) return;
    const int i0 = ib * 128;
    const int j0 = jb * 128;
    const bool diag = (ib == jb);
    const int tid  = threadIdx.x;
    const int wid  = tid >> 5;
    const int lane = tid & 31;
    const float* xb = x + (size_t)b * Cc * Nn;

    for (int L = tid; L < 2048; L += 256) {
        int c = L >> 5, q = L & 31;
        float4 v = *(const float4*)(xb + c * Nn + i0 + q * 4);
        *(float4*)(As + c * DSTRIDE + q * 4) = v;
        float4 w = *(const float4*)(xb + c * Nn + j0 + q * 4);
        *(float4*)(Bs + c * DSTRIDE + q * 4) = w;
    }
    if (tid < 128) {
        s_thri[tid] = g_thr[b * Nn + i0 + tid];
        s_sqi[tid]  = g_sq [b * Nn + i0 + tid];
    } else {
        int t = tid - 128;
        s_thrj[t] = g_thr[b * Nn + j0 + t];
        s_sqj[t]  = g_sq [b * Nn + j0 + t];
    }
    __syncthreads();

    int tx = tid & 15, ty = tid >> 4;
    unsigned long long acc2[8][4];
    #pragma unroll
    for (int i = 0; i < 8; i++)
        #pragma unroll
        for (int q = 0; q < 4; q++) acc2[i][q] = 0ull;

    #pragma unroll 4
    for (int kk = 0; kk < 64; kk++) {
        ulonglong2 bb0 = *(const ulonglong2*)(Bs + kk * DSTRIDE + tx * 8);
        ulonglong2 bb1 = *(const ulonglong2*)(Bs + kk * DSTRIDE + tx * 8 + 4);
        float4 a0 = *(const float4*)(As + kk * DSTRIDE + ty * 8);
        float4 a1 = *(const float4*)(As + kk * DSTRIDE + ty * 8 + 4);
        float a[8] = {a0.x, a0.y, a0.z, a0.w, a1.x, a1.y, a1.z, a1.w};
        #pragma unroll
        for (int i = 0; i < 8; i++) {
            unsigned long long ap = dup2(a[i]);
            fma2(acc2[i][0], ap, bb0.x);
            fma2(acc2[i][1], ap, bb0.y);
            fma2(acc2[i][2], ap, bb1.x);
            fma2(acc2[i][3], ap, bb1.y);
        }
    }

    // stage 2*acc tile into smem (reuse As/Bs; 128*129 <= 2*64*132)
    __syncthreads();
    float* Vs = sm;
    #pragma unroll
    for (int i = 0; i < 8; i++) {
        int rl = ty * 8 + i;
        float2 q0 = unpk(acc2[i][0]);
        float2 q1 = unpk(acc2[i][1]);
        float2 q2 = unpk(acc2[i][2]);
        float2 q3 = unpk(acc2[i][3]);
        float* vr = Vs + rl * VST + tx * 8;
        vr[0] = 2.f * q0.x; vr[1] = 2.f * q0.y;
        vr[2] = 2.f * q1.x; vr[3] = 2.f * q1.y;
        vr[4] = 2.f * q2.x; vr[5] = 2.f * q2.y;
        vr[6] = 2.f * q3.x; vr[7] = 2.f * q3.y;
    }
    __syncthreads();

    // i-side: warp scans rows wid*16..+15 (this block owns segment jb)
    for (int rr = 0; rr < 16; rr++) {
        int r = wid * 16 + rr;
        float sqi = s_sqi[r], thr = s_thri[r];
        float v[4]; unsigned msk[4]; int pc[4];
        int cnt = 0;
        #pragma unroll
        for (int s = 0; s < 4; s++) {
            int c = lane + 32 * s;
            float t2 = Vs[r * VST + c];
            v[s] = (t2 - sqi) - s_sqj[c];
            msk[s] = __ballot_sync(0xffffffffu, v[s] > thr);
            pc[s] = cnt; cnt += __popc(msk[s]);
        }
        int grow = b * Nn + i0 + r;
        if (lane == 0) g_tc[grow * NTILE + jb] = cnt;
        if (cnt) {
            size_t base = (size_t)grow * CAND_SLOTS + jb * SEG;
            #pragma unroll
            for (int s = 0; s < 4; s++) {
                if ((msk[s] >> lane) & 1u) {
                    int pos = pc[s] + __popc(msk[s] & ((1u << lane) - 1u));
                    if (pos < SEG) {
                        g_candv[base + pos] = v[s];
                        g_candi[base + pos] = j0 + lane + 32 * s;
                    }
                }
            }
        }
    }

    // j-side: warp scans columns wid*16..+15 (this block owns segment ib)
    if (!diag) {
        for (int cc = 0; cc < 16; cc++) {
            int c = wid * 16 + cc;
            float sqj = s_sqj[c], thr = s_thrj[c];
            float v[4]; unsigned msk[4]; int pc[4];
            int cnt = 0;
            #pragma unroll
            for (int s = 0; s < 4; s++) {
                int r = lane + 32 * s;
                float t2 = Vs[r * VST + c];
                v[s] = (t2 - sqj) - s_sqi[r];
                msk[s] = __ballot_sync(0xffffffffu, v[s] > thr);
                pc[s] = cnt; cnt += __popc(msk[s]);
            }
            int grow = b * Nn + j0 + c;
            if (lane == 0) g_tc[grow * NTILE + ib] = cnt;
            if (cnt) {
                size_t base = (size_t)grow * CAND_SLOTS + ib * SEG;
                #pragma unroll
                for (int s = 0; s < 4; s++) {
                    if ((msk[s] >> lane) & 1u) {
                        int pos = pc[s] + __popc(msk[s] & ((1u << lane) - 1u));
                        if (pos < SEG) {
                            g_candv[base + pos] = v[s];
                            g_candi[base + pos] = i0 + lane + 32 * s;
                        }
                    }
                }
            }
        }
    }
}

// ---------------- kernel 4: top-20 select (warp/row, count-compacted) -----
__global__ __launch_bounds__(256) void k_sel() {
    extern __shared__ float dsm[];
    int lane = threadIdx.x & 31;
    int w    = threadIdx.x >> 5;
    int row  = blockIdx.x * 8 + w;
    float* dv = dsm + (size_t)w * (2 * DCAP);
    int*   di = (int*)(dv + DCAP);

    const int* tc = g_tc + row * NTILE;
    int c0 = tc[lane];
    int c1 = tc[lane + 32];
    bool ovf = (c0 > SEG) || (c1 > SEG);
    ovf = __any_sync(0xffffffffu, ovf);

    int s0 = c0, s1 = c1;
    #pragma unroll
    for (int off = 1; off < 32; off <<= 1) {
        int y0 = __shfl_up_sync(0xffffffffu, s0, off);
        int y1 = __shfl_up_sync(0xffffffffu, s1, off);
        if (lane >= off) { s0 += y0; s1 += y1; }
    }
    int total0 = __shfl_sync(0xffffffffu, s0, 31);
    int total1 = __shfl_sync(0xffffffffu, s1, 31);
    int n = total0 + total1;
    int d0 = s0 - c0;
    int d1 = total0 + s1 - c1;

    if (!ovf && n >= Kk && n <= DCAP) {
        size_t rb = (size_t)row * CAND_SLOTS;
        const float* gv = g_candv + rb;
        const int*   gi = g_candi + rb;
        for (int e = 0; e < c0; e++) {
            dv[d0 + e] = gv[lane * SEG + e];
            di[d0 + e] = gi[lane * SEG + e];
        }
        for (int e = 0; e < c1; e++) {
            dv[d1 + e] = gv[(lane + 32) * SEG + e];
            di[d1 + e] = gi[(lane + 32) * SEG + e];
        }
        __syncwarp();

        int nseg = (n + 31) >> 5;
        float bv = -INFINITY; int bs = -1;
        for (int s = 0; s < nseg; s++) {
            int c = lane + (s << 5);
            if (c < n) { float vv = dv[c]; if (vv > bv) { bv = vv; bs = c; } }
        }
        for (int k = 0; k < Kk; k++) {
            unsigned key = f2key(bv);
            unsigned m = __reduce_max_sync(0xffffffffu, key);
            int cand = (key == m && bs >= 0) ? di[bs] : 0x7fffffff;
            int widx = __reduce_min_sync(0xffffffffu, cand);
            if (lane == 0) g_idx[row * Kk + k] = widx;
            if (cand == widx) {
                dv[bs] = -INFINITY;
                bv = -INFINITY; bs = -1;
                for (int s = 0; s < nseg; s++) {
                    int c = lane + (s << 5);
                    if (c < n) { float vv = dv[c]; if (vv > bv) { bv = vv; bs = c; } }
                }
            }
        }
    } else {
        // exact warp-local fallback: recompute the row (statistically never)
        int base = (row >> 13) * Nn;
        const float* xq = g_xt + (size_t)row * Cc;
        float sqq = g_sq[row];
        int chosen[Kk];
        for (int k = 0; k < Kk; k++) {
            float bv = -INFINITY; int bi = 0x7fffffff;
            for (int j = lane; j < Nn; j += 32) {
                bool skip = false;
                for (int q = 0; q < k; q++) if (chosen[q] == j) skip = true;
                if (skip) continue;
                const float* xj = g_xt + (size_t)(base + j) * Cc;
                float dot = 0.f;
                #pragma unroll
                for (int c = 0; c < Cc; c++) dot += xq[c] * xj[c];
                float val = 2.f * dot - sqq - g_sq[base + j];
                if (val > bv) { bv = val; bi = j; }
            }
            unsigned key = f2key(bv);
            unsigned m = __reduce_max_sync(0xffffffffu, key);
            int cand = (key == m) ? bi : 0x7fffffff;
            int widx = __reduce_min_sync(0xffffffffu, cand);
            if (lane == 0) g_idx[row * Kk + k] = widx;
            chosen[k] = widx;
        }
    }
}

// ---------------- kernel 5: per-point terms u = (W2-W1)·x, y = W1·x -------
__global__ void k_u(const float* __restrict__ W) {
    __shared__ float Wd[64 * 65];   // [c][o] W2-W1, stride 65
    __shared__ float Wa[64 * 65];   // [c][o] W1
    __shared__ float cs[4 * 64];
    int tid = threadIdx.x;
    for (int L = tid; L < 4096; L += 256) {
        int c = L & 63, o = L >> 6;
        float w1 = W[o * 128 + c];
        Wd[c * 65 + o] = W[o * 128 + 64 + c] - w1;
        Wa[c * 65 + o] = w1;
    }
    int p0 = blockIdx.x * 4;
    {
        int pi = tid >> 6, c = tid & 63;
        cs[pi * 64 + c] = g_xt[(size_t)(p0 + pi) * 64 + c];
    }
    __syncthreads();
    int o = tid & 63, pi = tid >> 6;
    float a = 0.f, y = 0.f;
    #pragma unroll
    for (int c = 0; c < 64; c++) {
        float xv = cs[pi * 64 + c];
        a += Wd[c * 65 + o] * xv;
        y += Wa[c * 65 + o] * xv;
    }
    g_u[(size_t)(p0 + pi) * 64 + o] = a;
    g_y[(size_t)(p0 + pi) * 64 + o] = y;
}

// ---------------- kernel 6/8: edge gather  h = Y[nbr] + u[cen] ------------
// Warp per point: 20 neighbor Y-rows gathered (L2-resident, 256B/line).
// MODE 0: accumulate per-channel sum/sumsq. MODE 1: max/min over k, BN +
// LeakyReLU (monotone; sc<0 handled via min), transposed coalesced output.
template<int MODE>
__global__ __launch_bounds__(256) void k_conv2(float* __restrict__ out) {
    __shared__ float ssum[64];
    __shared__ float ssq[64];
    __shared__ float ssc[64];
    __shared__ float ssh[64];
    __shared__ float hmax[8][66];

    int tid  = threadIdx.x;
    int w    = tid >> 5;
    int lane = tid & 31;
    int p    = blockIdx.x * 8 + w;
    int b    = p >> 13;

    if (MODE == 0) { if (tid < 64) { ssum[tid] = 0.f; ssq[tid] = 0.f; } }
    else           { if (tid < 64) { ssc[tid] = g_sc[tid]; ssh[tid] = g_sh[tid]; } }
    __syncthreads();

    float2 uv = *(const float2*)(g_u + (size_t)p * 64 + lane * 2);
    float s0 = 0.f, s1 = 0.f, q0 = 0.f, q1 = 0.f;
    float m0 = -INFINITY, m1 = -INFINITY, n0 = INFINITY, n1 = INFINITY;

    #pragma unroll 4
    for (int k = 0; k < Kk; k++) {
        int j = g_idx[p * Kk + k];
        float2 y = *(const float2*)(g_y + (size_t)(b * Nn + j) * 64 + lane * 2);
        float h0 = y.x + uv.x;
        float h1 = y.y + uv.y;
        if (MODE == 0) {
            s0 += h0; s1 += h1;
            q0 += h0 * h0; q1 += h1 * h1;
        } else {
            m0 = fmaxf(m0, h0); m1 = fmaxf(m1, h1);
            n0 = fminf(n0, h0); n1 = fminf(n1, h1);
        }
    }

    if (MODE == 0) {
        atomicAdd(&ssum[lane * 2],     s0);
        atomicAdd(&ssum[lane * 2 + 1], s1);
        atomicAdd(&ssq [lane * 2],     q0);
        atomicAdd(&ssq [lane * 2 + 1], q1);
        __syncthreads();
        if (tid < 64) {
            atomicAdd(&g_sum[tid],   (double)ssum[tid]);
            atomicAdd(&g_sumsq[tid], (double)ssq[tid]);
        }
    } else {
        float c0 = ssc[lane * 2],     h0s = ssh[lane * 2];
        float c1 = ssc[lane * 2 + 1], h1s = ssh[lane * 2 + 1];
        float v0 = (c0 >= 0.f) ? m0 : n0;
        float v1 = (c1 >= 0.f) ? m1 : n1;
        float r0 = c0 * v0 + h0s;
        float r1 = c1 * v1 + h1s;
        r0 = (r0 >= 0.f) ? r0 : 0.2f * r0;
        r1 = (r1 >= 0.f) ? r1 : 0.2f * r1;
        hmax[w][lane * 2]     = r0;
        hmax[w][lane * 2 + 1] = r1;
        __syncthreads();
        for (int task = tid; task < 512; task += 256) {
            int o  = task >> 3;
            int pp = task & 7;
            int gp = blockIdx.x * 8 + pp;
            int bb = gp >> 13, nn = gp & (Nn - 1);
            out[((size_t)bb * 64 + o) * Nn + nn] = hmax[pp][o];
        }
    }
}

// ---------------- kernel 7: finalize BN scale/shift ----------------
__global__ void k_fin(const float* __restrict__ gamma, const float* __restrict__ beta) {
    int o = threadIdx.x;
    if (o < Oo) {
        double cnt  = (double)MROWS;
        double mean = g_sum[o] / cnt;
        double var  = g_sumsq[o] / cnt - mean * mean;
        float inv = rsqrtf((float)(var + 1e-5));
        float sc  = gamma[o] * inv;
        g_sc[o] = sc;
        g_sh[o] = beta[o] - (float)mean * sc;
    }
}

// ---------------- launcher ----------------
extern "C" void kernel_launch(void* const* d_in, const int* in_sizes, int n_in,
                              void* d_out, int out_size) {
    const float* x     = (const float*)d_in[0];
    const float* W     = (const float*)d_in[1];
    const float* gamma = (const float*)d_in[2];
    const float* beta  = (const float*)d_in[3];
    float* out = (float*)d_out;

    const int SMEM_GEMM = 2 * 64 * DSTRIDE * sizeof(float);          // 67584
    const int SMEM_SEL  = 8 * 2 * DCAP * sizeof(float);              // 98304

    cudaFuncSetAttribute(k_samp,     cudaFuncAttributeMaxDynamicSharedMemorySize, SMEM_GEMM);
    cudaFuncSetAttribute(k_dist_sym, cudaFuncAttributeMaxDynamicSharedMemorySize, SMEM_GEMM);
    cudaFuncSetAttribute(k_sel,      cudaFuncAttributeMaxDynamicSharedMemorySize, SMEM_SEL);

    k_zero<<<1, 64>>>();
    k_prep<<<NPOINTS / 256, 256>>>(x);
    k_samp<<<dim3(2, Nn / 128, Bb), 256, SMEM_GEMM>>>(x);
    k_thr<<<NPOINTS / 8, 256>>>();
    k_dist_sym<<<dim3(Nn / 128, Nn / 128, Bb), 256, SMEM_GEMM>>>(x);
    k_sel<<<NPOINTS / 8, 256, SMEM_SEL>>>();
    k_u<<<NPOINTS / 4, 256>>>(W);
    k_conv2<0><<<NPOINTS / 8, 256>>>(out);
    k_fin<<<1, 64>>>(gamma, beta);
    k_conv2<1><<<NPOINTS / 8, 256>>>(out);
}

// round 17
// speedup vs baseline: 1.5480x; 1.5480x over previous
#include <cuda_runtime.h>
#include <math.h>

// Problem constants
#define Bb 2
#define Cc 64
#define Nn 8192
#define Oo 64
#define Kk 20
#define NPOINTS (Bb * Nn)            // 16384
#define MROWS   (NPOINTS * Kk)       // 327680
#define SEG 48                       // slots per (row, column-tile) segment
#define NTILE 64                     // column tiles per row
#define CAND_SLOTS (NTILE * SEG)     // 3072 slots per row
#define DCAP 1536                    // dense per-row candidate cap in k_sel

// ---------------- scratch (device globals; allocation-free) ----------------
__device__ float  g_xt[NPOINTS * Cc];   // [B*N][C]   transposed points
__device__ float  g_sq[NPOINTS];        // ||x||^2 per point
__device__ float  g_xsT[Bb * Cc * 256]; // gathered sample points, [b][c][s]
__device__ float  g_sqs[Bb * 256];      // sample sq
__device__ float  g_sdist[NPOINTS * 256]; // sample distances per row
__device__ float  g_thr[NPOINTS];       // per-row threshold
__device__ float  g_candv[(size_t)NPOINTS * CAND_SLOTS];
__device__ int    g_candi[(size_t)NPOINTS * CAND_SLOTS];
__device__ int    g_tc[NPOINTS * NTILE]; // per (row, tile) survivor count
__device__ int    g_idx[MROWS];         // top-K indices, [B*N][K]
__device__ float  g_u[NPOINTS * Oo];    // center term (W2-W1)·cen
__device__ float  g_y[NPOINTS * Oo];    // neighbor term W1·x per point
__device__ double g_sum[Oo];
__device__ double g_sumsq[Oo];
__device__ float  g_sc[Oo];
__device__ float  g_sh[Oo];

// monotonic float <-> sortable uint mapping
__device__ __forceinline__ unsigned f2key(float f) {
    unsigned u = __float_as_uint(f);
    return (u & 0x80000000u) ? ~u : (u | 0x80000000u);
}
__device__ __forceinline__ float key2f(unsigned m) {
    return __uint_as_float((m & 0x80000000u) ? (m & 0x7FFFFFFFu) : ~m);
}

// ---------------- packed fp32x2 helpers (B300 FFMA2 path, PTX-only) --------
__device__ __forceinline__ unsigned long long dup2(float a) {
    unsigned long long r;
    asm("mov.b64 %0, {%1, %1};" : "=l"(r) : "f"(a));
    return r;
}
__device__ __forceinline__ void fma2(unsigned long long& d, unsigned long long a,
                                     unsigned long long b) {
    asm("fma.rn.f32x2 %0, %1, %2, %0;" : "+l"(d) : "l"(a), "l"(b));
}
__device__ __forceinline__ float2 unpk(unsigned long long v) {
    float2 r;
    asm("mov.b64 {%0, %1}, %2;" : "=f"(r.x), "=f"(r.y) : "l"(v));
    return r;
}

// ---------------- kernel 0: zero accumulators ----------------
__global__ void k_zero() {
    int t = threadIdx.x;
    if (t < Oo) { g_sum[t] = 0.0; g_sumsq[t] = 0.0; }
}

// ---------------- kernel 1: transpose x -> xt, sq, gather samples ---------
// Sample positions: pos(s) = s*32 + (s&31), s in [0,256).
__global__ void k_prep(const float* __restrict__ x) {
    int p = blockIdx.x * 256 + threadIdx.x;   // 0..16383
    int b = p >> 13;
    int n = p & (Nn - 1);
    const float* xb = x + (size_t)b * Cc * Nn;
    bool is_s = ((n & 31) == ((n >> 5) & 31));
    int s = n >> 5;
    float sm = 0.f;
    #pragma unroll
    for (int c = 0; c < Cc; c++) {
        float v = xb[c * Nn + n];
        sm += v * v;
        g_xt[(size_t)p * Cc + c] = v;
        if (is_s) g_xsT[(b * Cc + c) * 256 + s] = v;
    }
    g_sq[p] = sm;
    if (is_s) g_sqs[b * 256 + s] = sm;
}

// ---------------- kernel 2a: sample-dist GEMM (rows x 256 samples) --------
#define DSTRIDE 132
__global__ void k_samp(const float* __restrict__ x) {
    extern __shared__ float sm[];
    float* As = sm;
    float* Bs = sm + 64 * DSTRIDE;
    const int b  = blockIdx.z;
    const int i0 = blockIdx.y * 128;
    const int j0 = blockIdx.x * 128;
    const int tid = threadIdx.x;
    const float* xb = x + (size_t)b * Cc * Nn;

    for (int L = tid; L < 2048; L += 256) {
        int c = L >> 5, q = L & 31;
        float4 v = *(const float4*)(xb + c * Nn + i0 + q * 4);
        *(float4*)(As + c * DSTRIDE + q * 4) = v;
        float4 w = *(const float4*)(g_xsT + (b * Cc + c) * 256 + j0 + q * 4);
        *(float4*)(Bs + c * DSTRIDE + q * 4) = w;
    }
    __syncthreads();

    int tx = tid & 15, ty = tid >> 4;
    unsigned long long acc2[8][4];
    #pragma unroll
    for (int i = 0; i < 8; i++)
        #pragma unroll
        for (int q = 0; q < 4; q++) acc2[i][q] = 0ull;

    #pragma unroll 4
    for (int kk = 0; kk < 64; kk++) {
        ulonglong2 bb0 = *(const ulonglong2*)(Bs + kk * DSTRIDE + tx * 8);
        ulonglong2 bb1 = *(const ulonglong2*)(Bs + kk * DSTRIDE + tx * 8 + 4);
        float4 a0 = *(const float4*)(As + kk * DSTRIDE + ty * 8);
        float4 a1 = *(const float4*)(As + kk * DSTRIDE + ty * 8 + 4);
        float a[8] = {a0.x, a0.y, a0.z, a0.w, a1.x, a1.y, a1.z, a1.w};
        #pragma unroll
        for (int i = 0; i < 8; i++) {
            unsigned long long ap = dup2(a[i]);
            fma2(acc2[i][0], ap, bb0.x);
            fma2(acc2[i][1], ap, bb0.y);
            fma2(acc2[i][2], ap, bb1.x);
            fma2(acc2[i][3], ap, bb1.y);
        }
    }

    float sqj[8];
    #pragma unroll
    for (int j = 0; j < 8; j++) sqj[j] = g_sqs[b * 256 + j0 + tx * 8 + j];
    #pragma unroll
    for (int i = 0; i < 8; i++) {
        float sqi = g_sq[b * Nn + i0 + ty * 8 + i];
        float* dst = g_sdist + (size_t)(b * Nn + i0 + ty * 8 + i) * 256 + j0 + tx * 8;
        float2 p0 = unpk(acc2[i][0]);
        float2 p1 = unpk(acc2[i][1]);
        float2 p2 = unpk(acc2[i][2]);
        float2 p3 = unpk(acc2[i][3]);
        float4 r0, r1;
        r0.x = 2.f * p0.x - sqi - sqj[0];
        r0.y = 2.f * p0.y - sqi - sqj[1];
        r0.z = 2.f * p1.x - sqi - sqj[2];
        r0.w = 2.f * p1.y - sqi - sqj[3];
        r1.x = 2.f * p2.x - sqi - sqj[4];
        r1.y = 2.f * p2.y - sqi - sqj[5];
        r1.z = 2.f * p3.x - sqi - sqj[6];
        r1.w = 2.f * p3.y - sqi - sqj[7];
        *(float4*)dst = r0;
        *(float4*)(dst + 4) = r1;
    }
}

// ---------------- kernel 2b: per-row threshold = 12th largest sample ------
__global__ __launch_bounds__(256) void k_thr() {
    int lane = threadIdx.x & 31;
    int row  = blockIdx.x * 8 + (threadIdx.x >> 5);
    const float* sd = g_sdist + (size_t)row * 256;
    float lv[8];
    #pragma unroll
    for (int s = 0; s < 8; s++) lv[s] = sd[lane + 32 * s];
    for (int k = 0; ; k++) {
        float lmax = lv[0];
        #pragma unroll
        for (int s = 1; s < 8; s++) lmax = fmaxf(lmax, lv[s]);
        unsigned key = f2key(lmax);
        unsigned m = __reduce_max_sync(0xffffffffu, key);
        if (k == 11) { if (lane == 0) g_thr[row] = key2f(m); break; }
        int win = __ffs(__ballot_sync(0xffffffffu, key == m)) - 1;
        if (lane == win) {
            bool done = false;
            #pragma unroll
            for (int s = 0; s < 8; s++)
                if (!done && lv[s] == lmax) { lv[s] = -INFINITY; done = true; }
        }
    }
}

// ---------------- kernel 3: symmetric dist GEMM + fixed-slot filter -------
// Upper-triangle tiles only (jb >= ib). Survivors written directly to
// reserved per-(row,tile) global slots; exactly one writer per segment,
// NO atomics. Counts in g_tc; overflow detected in k_sel -> exact fallback.
#define VST 129
__global__ __launch_bounds__(256) void k_dist_sym(const float* __restrict__ x) {
    extern __shared__ float sm[];
    float* As = sm;
    float* Bs = sm + 64 * DSTRIDE;
    __shared__ float s_thri[128], s_thrj[128], s_sqi[128], s_sqj[128];

    const int b  = blockIdx.z;
    const int ib = blockIdx.y;
    const int jb = blockIdx.x;
    if (jb < ib) return;
    const int i0 = ib * 128;
    const int j0 = jb * 128;
    const bool diag = (ib == jb);
    const int tid  = threadIdx.x;
    const int wid  = tid >> 5;
    const int lane = tid & 31;
    const float* xb = x + (size_t)b * Cc * Nn;

    for (int L = tid; L < 2048; L += 256) {
        int c = L >> 5, q = L & 31;
        float4 v = *(const float4*)(xb + c * Nn + i0 + q * 4);
        *(float4*)(As + c * DSTRIDE + q * 4) = v;
        float4 w = *(const float4*)(xb + c * Nn + j0 + q * 4);
        *(float4*)(Bs + c * DSTRIDE + q * 4) = w;
    }
    if (tid < 128) {
        s_thri[tid] = g_thr[b * Nn + i0 + tid];
        s_sqi[tid]  = g_sq [b * Nn + i0 + tid];
    } else {
        int t = tid - 128;
        s_thrj[t] = g_thr[b * Nn + j0 + t];
        s_sqj[t]  = g_sq [b * Nn + j0 + t];
    }
    __syncthreads();

    int tx = tid & 15, ty = tid >> 4;
    unsigned long long acc2[8][4];
    #pragma unroll
    for (int i = 0; i < 8; i++)
        #pragma unroll
        for (int q = 0; q < 4; q++) acc2[i][q] = 0ull;

    #pragma unroll 4
    for (int kk = 0; kk < 64; kk++) {
        ulonglong2 bb0 = *(const ulonglong2*)(Bs + kk * DSTRIDE + tx * 8);
        ulonglong2 bb1 = *(const ulonglong2*)(Bs + kk * DSTRIDE + tx * 8 + 4);
        float4 a0 = *(const float4*)(As + kk * DSTRIDE + ty * 8);
        float4 a1 = *(const float4*)(As + kk * DSTRIDE + ty * 8 + 4);
        float a[8] = {a0.x, a0.y, a0.z, a0.w, a1.x, a1.y, a1.z, a1.w};
        #pragma unroll
        for (int i = 0; i < 8; i++) {
            unsigned long long ap = dup2(a[i]);
            fma2(acc2[i][0], ap, bb0.x);
            fma2(acc2[i][1], ap, bb0.y);
            fma2(acc2[i][2], ap, bb1.x);
            fma2(acc2[i][3], ap, bb1.y);
        }
    }

    // stage 2*acc tile into smem (reuse As/Bs; 128*129 <= 2*64*132)
    __syncthreads();
    float* Vs = sm;
    #pragma unroll
    for (int i = 0; i < 8; i++) {
        int rl = ty * 8 + i;
        float2 q0 = unpk(acc2[i][0]);
        float2 q1 = unpk(acc2[i][1]);
        float2 q2 = unpk(acc2[i][2]);
        float2 q3 = unpk(acc2[i][3]);
        float* vr = Vs + rl * VST + tx * 8;
        vr[0] = 2.f * q0.x; vr[1] = 2.f * q0.y;
        vr[2] = 2.f * q1.x; vr[3] = 2.f * q1.y;
        vr[4] = 2.f * q2.x; vr[5] = 2.f * q2.y;
        vr[6] = 2.f * q3.x; vr[7] = 2.f * q3.y;
    }
    __syncthreads();

    // i-side: warp scans rows wid*16..+15 (this block owns segment jb)
    for (int rr = 0; rr < 16; rr++) {
        int r = wid * 16 + rr;
        float sqi = s_sqi[r], thr = s_thri[r];
        float t2v[4];
        #pragma unroll
        for (int s = 0; s < 4; s++) t2v[s] = Vs[r * VST + lane + 32 * s];
        float v[4]; unsigned msk[4]; int pc[4];
        int cnt = 0;
        #pragma unroll
        for (int s = 0; s < 4; s++) {
            v[s] = (t2v[s] - sqi) - s_sqj[lane + 32 * s];
            msk[s] = __ballot_sync(0xffffffffu, v[s] > thr);
            pc[s] = cnt; cnt += __popc(msk[s]);
        }
        int grow = b * Nn + i0 + r;
        if (lane == 0) g_tc[grow * NTILE + jb] = cnt;
        if (cnt) {
            size_t base = (size_t)grow * CAND_SLOTS + jb * SEG;
            #pragma unroll
            for (int s = 0; s < 4; s++) {
                if ((msk[s] >> lane) & 1u) {
                    int pos = pc[s] + __popc(msk[s] & ((1u << lane) - 1u));
                    if (pos < SEG) {
                        g_candv[base + pos] = v[s];
                        g_candi[base + pos] = j0 + lane + 32 * s;
                    }
                }
            }
        }
    }

    // j-side: warp scans columns wid*16..+15 (this block owns segment ib)
    if (!diag) {
        for (int cc = 0; cc < 16; cc++) {
            int c = wid * 16 + cc;
            float sqj = s_sqj[c], thr = s_thrj[c];
            float t2v[4];
            #pragma unroll
            for (int s = 0; s < 4; s++) t2v[s] = Vs[(lane + 32 * s) * VST + c];
            float v[4]; unsigned msk[4]; int pc[4];
            int cnt = 0;
            #pragma unroll
            for (int s = 0; s < 4; s++) {
                v[s] = (t2v[s] - sqj) - s_sqi[lane + 32 * s];
                msk[s] = __ballot_sync(0xffffffffu, v[s] > thr);
                pc[s] = cnt; cnt += __popc(msk[s]);
            }
            int grow = b * Nn + j0 + c;
            if (lane == 0) g_tc[grow * NTILE + ib] = cnt;
            if (cnt) {
                size_t base = (size_t)grow * CAND_SLOTS + ib * SEG;
                #pragma unroll
                for (int s = 0; s < 4; s++) {
                    if ((msk[s] >> lane) & 1u) {
                        int pos = pc[s] + __popc(msk[s] & ((1u << lane) - 1u));
                        if (pos < SEG) {
                            g_candv[base + pos] = v[s];
                            g_candi[base + pos] = i0 + lane + 32 * s;
                        }
                    }
                }
            }
        }
    }
}

// ---------------- kernel 4: top-20 select (warp/row, count-compacted) -----
__global__ __launch_bounds__(256) void k_sel() {
    extern __shared__ float dsm[];
    int lane = threadIdx.x & 31;
    int w    = threadIdx.x >> 5;
    int row  = blockIdx.x * 8 + w;
    float* dv = dsm + (size_t)w * (2 * DCAP);
    int*   di = (int*)(dv + DCAP);

    const int* tc = g_tc + row * NTILE;
    int c0 = tc[lane];
    int c1 = tc[lane + 32];
    bool ovf = (c0 > SEG) || (c1 > SEG);
    ovf = __any_sync(0xffffffffu, ovf);

    int s0 = c0, s1 = c1;
    #pragma unroll
    for (int off = 1; off < 32; off <<= 1) {
        int y0 = __shfl_up_sync(0xffffffffu, s0, off);
        int y1 = __shfl_up_sync(0xffffffffu, s1, off);
        if (lane >= off) { s0 += y0; s1 += y1; }
    }
    int total0 = __shfl_sync(0xffffffffu, s0, 31);
    int total1 = __shfl_sync(0xffffffffu, s1, 31);
    int n = total0 + total1;
    int d0 = s0 - c0;
    int d1 = total0 + s1 - c1;

    if (!ovf && n >= Kk && n <= DCAP) {
        size_t rb = (size_t)row * CAND_SLOTS;
        const float* gv = g_candv + rb;
        const int*   gi = g_candi + rb;
        for (int e = 0; e < c0; e++) {
            dv[d0 + e] = gv[lane * SEG + e];
            di[d0 + e] = gi[lane * SEG + e];
        }
        for (int e = 0; e < c1; e++) {
            dv[d1 + e] = gv[(lane + 32) * SEG + e];
            di[d1 + e] = gi[(lane + 32) * SEG + e];
        }
        __syncwarp();

        int nseg = (n + 31) >> 5;
        float bv = -INFINITY; int bs = -1;
        for (int s = 0; s < nseg; s++) {
            int c = lane + (s << 5);
            if (c < n) { float vv = dv[c]; if (vv > bv) { bv = vv; bs = c; } }
        }
        for (int k = 0; k < Kk; k++) {
            unsigned key = f2key(bv);
            unsigned m = __reduce_max_sync(0xffffffffu, key);
            int cand = (key == m && bs >= 0) ? di[bs] : 0x7fffffff;
            int widx = __reduce_min_sync(0xffffffffu, cand);
            if (lane == 0) g_idx[row * Kk + k] = widx;
            if (cand == widx) {
                dv[bs] = -INFINITY;
                bv = -INFINITY; bs = -1;
                for (int s = 0; s < nseg; s++) {
                    int c = lane + (s << 5);
                    if (c < n) { float vv = dv[c]; if (vv > bv) { bv = vv; bs = c; } }
                }
            }
        }
    } else {
        // exact warp-local fallback: recompute the row (statistically never)
        int base = (row >> 13) * Nn;
        const float* xq = g_xt + (size_t)row * Cc;
        float sqq = g_sq[row];
        int chosen[Kk];
        for (int k = 0; k < Kk; k++) {
            float bv = -INFINITY; int bi = 0x7fffffff;
            for (int j = lane; j < Nn; j += 32) {
                bool skip = false;
                for (int q = 0; q < k; q++) if (chosen[q] == j) skip = true;
                if (skip) continue;
                const float* xj = g_xt + (size_t)(base + j) * Cc;
                float dot = 0.f;
                #pragma unroll
                for (int c = 0; c < Cc; c++) dot += xq[c] * xj[c];
                float val = 2.f * dot - sqq - g_sq[base + j];
                if (val > bv) { bv = val; bi = j; }
            }
            unsigned key = f2key(bv);
            unsigned m = __reduce_max_sync(0xffffffffu, key);
            int cand = (key == m) ? bi : 0x7fffffff;
            int widx = __reduce_min_sync(0xffffffffu, cand);
            if (lane == 0) g_idx[row * Kk + k] = widx;
            chosen[k] = widx;
        }
    }
}

// ---------------- kernel 5: per-point terms u = (W2-W1)·x, y = W1·x -------
__global__ void k_u(const float* __restrict__ W) {
    __shared__ float Wd[64 * 65];   // [c][o] W2-W1, stride 65
    __shared__ float Wa[64 * 65];   // [c][o] W1
    __shared__ float cs[4 * 64];
    int tid = threadIdx.x;
    for (int L = tid; L < 4096; L += 256) {
        int c = L & 63, o = L >> 6;
        float w1 = W[o * 128 + c];
        Wd[c * 65 + o] = W[o * 128 + 64 + c] - w1;
        Wa[c * 65 + o] = w1;
    }
    int p0 = blockIdx.x * 4;
    {
        int pi = tid >> 6, c = tid & 63;
        cs[pi * 64 + c] = g_xt[(size_t)(p0 + pi) * 64 + c];
    }
    __syncthreads();
    int o = tid & 63, pi = tid >> 6;
    float a = 0.f, y = 0.f;
    #pragma unroll
    for (int c = 0; c < 64; c++) {
        float xv = cs[pi * 64 + c];
        a += Wd[c * 65 + o] * xv;
        y += Wa[c * 65 + o] * xv;
    }
    g_u[(size_t)(p0 + pi) * 64 + o] = a;
    g_y[(size_t)(p0 + pi) * 64 + o] = y;
}

// ---------------- kernel 6/8: edge gather  h = Y[nbr] + u[cen] ------------
// Warp per point. All 20 neighbor indices prefetched in ONE coalesced load
// (lanes 0..19) and distributed via shfl -> the 20 Y-row gathers are fully
// independent (MLP~20, L2-resident). MODE 0: per-channel sum/sumsq.
// MODE 1: max/min over k, BN + LeakyReLU (monotone; sc<0 via min).
template<int MODE>
__global__ __launch_bounds__(256) void k_conv2(float* __restrict__ out) {
    __shared__ float ssum[64];
    __shared__ float ssq[64];
    __shared__ float ssc[64];
    __shared__ float ssh[64];
    __shared__ float hmax[8][66];

    int tid  = threadIdx.x;
    int w    = tid >> 5;
    int lane = tid & 31;
    int p    = blockIdx.x * 8 + w;
    int b    = p >> 13;

    if (MODE == 0) { if (tid < 64) { ssum[tid] = 0.f; ssq[tid] = 0.f; } }
    else           { if (tid < 64) { ssc[tid] = g_sc[tid]; ssh[tid] = g_sh[tid]; } }
    __syncthreads();

    // one coalesced index prefetch for the whole warp
    int myidx = (lane < Kk) ? g_idx[p * Kk + lane] : 0;

    float2 uv = *(const float2*)(g_u + (size_t)p * 64 + lane * 2);
    float s0 = 0.f, s1 = 0.f, q0 = 0.f, q1 = 0.f;
    float m0 = -INFINITY, m1 = -INFINITY, n0 = INFINITY, n1 = INFINITY;

    #pragma unroll
    for (int k = 0; k < Kk; k++) {
        int j = __shfl_sync(0xffffffffu, myidx, k);
        float2 y = *(const float2*)(g_y + (size_t)(b * Nn + j) * 64 + lane * 2);
        float h0 = y.x + uv.x;
        float h1 = y.y + uv.y;
        if (MODE == 0) {
            s0 += h0; s1 += h1;
            q0 += h0 * h0; q1 += h1 * h1;
        } else {
            m0 = fmaxf(m0, h0); m1 = fmaxf(m1, h1);
            n0 = fminf(n0, h0); n1 = fminf(n1, h1);
        }
    }

    if (MODE == 0) {
        atomicAdd(&ssum[lane * 2],     s0);
        atomicAdd(&ssum[lane * 2 + 1], s1);
        atomicAdd(&ssq [lane * 2],     q0);
        atomicAdd(&ssq [lane * 2 + 1], q1);
        __syncthreads();
        if (tid < 64) {
            atomicAdd(&g_sum[tid],   (double)ssum[tid]);
            atomicAdd(&g_sumsq[tid], (double)ssq[tid]);
        }
    } else {
        float c0 = ssc[lane * 2],     h0s = ssh[lane * 2];
        float c1 = ssc[lane * 2 + 1], h1s = ssh[lane * 2 + 1];
        float v0 = (c0 >= 0.f) ? m0 : n0;
        float v1 = (c1 >= 0.f) ? m1 : n1;
        float r0 = c0 * v0 + h0s;
        float r1 = c1 * v1 + h1s;
        r0 = (r0 >= 0.f) ? r0 : 0.2f * r0;
        r1 = (r1 >= 0.f) ? r1 : 0.2f * r1;
        hmax[w][lane * 2]     = r0;
        hmax[w][lane * 2 + 1] = r1;
        __syncthreads();
        for (int task = tid; task < 512; task += 256) {
            int o  = task >> 3;
            int pp = task & 7;
            int gp = blockIdx.x * 8 + pp;
            int bb = gp >> 13, nn = gp & (Nn - 1);
            out[((size_t)bb * 64 + o) * Nn + nn] = hmax[pp][o];
        }
    }
}

// ---------------- kernel 7: finalize BN scale/shift ----------------
__global__ void k_fin(const float* __restrict__ gamma, const float* __restrict__ beta) {
    int o = threadIdx.x;
    if (o < Oo) {
        double cnt  = (double)MROWS;
        double mean = g_sum[o] / cnt;
        double var  = g_sumsq[o] / cnt - mean * mean;
        float inv = rsqrtf((float)(var + 1e-5));
        float sc  = gamma[o] * inv;
        g_sc[o] = sc;
        g_sh[o] = beta[o] - (float)mean * sc;
    }
}

// ---------------- launcher ----------------
extern "C" void kernel_launch(void* const* d_in, const int* in_sizes, int n_in,
                              void* d_out, int out_size) {
    const float* x     = (const float*)d_in[0];
    const float* W     = (const float*)d_in[1];
    const float* gamma = (const float*)d_in[2];
    const float* beta  = (const float*)d_in[3];
    float* out = (float*)d_out;

    const int SMEM_GEMM = 2 * 64 * DSTRIDE * sizeof(float);          // 67584
    const int SMEM_SEL  = 8 * 2 * DCAP * sizeof(float);              // 98304

    cudaFuncSetAttribute(k_samp,     cudaFuncAttributeMaxDynamicSharedMemorySize, SMEM_GEMM);
    cudaFuncSetAttribute(k_dist_sym, cudaFuncAttributeMaxDynamicSharedMemorySize, SMEM_GEMM);
    cudaFuncSetAttribute(k_sel,      cudaFuncAttributeMaxDynamicSharedMemorySize, SMEM_SEL);

    k_zero<<<1, 64>>>();
    k_prep<<<NPOINTS / 256, 256>>>(x);
    k_samp<<<dim3(2, Nn / 128, Bb), 256, SMEM_GEMM>>>(x);
    k_thr<<<NPOINTS / 8, 256>>>();
    k_dist_sym<<<dim3(Nn / 128, Nn / 128, Bb), 256, SMEM_GEMM>>>(x);
    k_sel<<<NPOINTS / 8, 256, SMEM_SEL>>>();
    k_u<<<NPOINTS / 4, 256>>>(W);
    k_conv2<0><<<NPOINTS / 8, 256>>>(out);
    k_fin<<<1, 64>>>(gamma, beta);
    k_conv2<1><<<NPOINTS / 8, 256>>>(out);
}